// round 3
// baseline (speedup 1.0000x reference)
#include <cuda_runtime.h>

// Problem constants (B=1, N=4, C=16, D=64, H=128, W=128)
#define NCTX 4
#define CH   16
#define VOX  (64 * 128 * 128)   // 1,048,576 voxels
#define TPB  256

__global__ __launch_bounds__(TPB, 6) void volattn3d_kernel(
    const float* __restrict__ q,      // [C][V]
    const float* __restrict__ k,      // [N][C][V]
    const float* __restrict__ v,      // [N][C][V]
    const float* __restrict__ w_proj, // [C][C]
    const float* __restrict__ b_proj, // [C]
    float* __restrict__ out)          // [C][V]
{
    __shared__ float sw[CH * CH];
    __shared__ float sb[CH];
    {
        int t = threadIdx.x;
        if (t < CH * CH) sw[t] = w_proj[t];
        if (t < CH)      sb[t] = b_proj[t];
    }
    __syncthreads();

    const int p = blockIdx.x * TPB + threadIdx.x;   // voxel index
    const float* qp = q + p;
    const float* kp = k + p;
    const float* vp = v + p;

    // ---- scores[n] = (q . k_n), c-outer so q is never array-resident ----
    float sc0 = 0.f, sc1 = 0.f, sc2 = 0.f, sc3 = 0.f;
#pragma unroll
    for (int c = 0; c < CH; ++c) {
        const float qv = __ldcs(qp + c * VOX);
        sc0 = fmaf(qv, __ldcs(kp + (0 * CH + c) * VOX), sc0);
        sc1 = fmaf(qv, __ldcs(kp + (1 * CH + c) * VOX), sc1);
        sc2 = fmaf(qv, __ldcs(kp + (2 * CH + c) * VOX), sc2);
        sc3 = fmaf(qv, __ldcs(kp + (3 * CH + c) * VOX), sc3);
    }
    sc0 *= 0.25f; sc1 *= 0.25f; sc2 *= 0.25f; sc3 *= 0.25f;

    // ---- softmax over n=4 ----
    const float mx = fmaxf(fmaxf(sc0, sc1), fmaxf(sc2, sc3));
    sc0 = __expf(sc0 - mx);
    sc1 = __expf(sc1 - mx);
    sc2 = __expf(sc2 - mx);
    sc3 = __expf(sc3 - mx);
    const float rs = __frcp_rn(sc0 + sc1 + sc2 + sc3);
    sc0 *= rs; sc1 *= rs; sc2 *= rs; sc3 *= rs;

    // ---- x[c] = sum_n attn[n] * v[n][c] ----
    float x[CH];
#pragma unroll
    for (int c = 0; c < CH; ++c) {
        float a = sc0 * __ldcs(vp + (0 * CH + c) * VOX);
        a = fmaf(sc1, __ldcs(vp + (1 * CH + c) * VOX), a);
        a = fmaf(sc2, __ldcs(vp + (2 * CH + c) * VOX), a);
        a = fmaf(sc3, __ldcs(vp + (3 * CH + c) * VOX), a);
        x[c] = a;
    }

    // ---- out[o] = sum_c w[o][c] * x[c] + b[o] ----
    float* op = out + p;
#pragma unroll
    for (int o = 0; o < CH; ++o) {
        float acc = sb[o];
#pragma unroll
        for (int c = 0; c < CH; ++c)
            acc = fmaf(sw[o * CH + c], x[c], acc);
        __stcs(op + o * VOX, acc);
    }
}

extern "C" void kernel_launch(void* const* d_in, const int* in_sizes, int n_in,
                              void* d_out, int out_size) {
    const float* q      = (const float*)d_in[0];
    const float* k      = (const float*)d_in[1];
    const float* v      = (const float*)d_in[2];
    const float* w_proj = (const float*)d_in[3];
    const float* b_proj = (const float*)d_in[4];
    float* out = (float*)d_out;

    const int grid = VOX / TPB;   // 4096
    volattn3d_kernel<<<grid, TPB>>>(q, k, v, w_proj, b_proj, out);
}